// round 3
// baseline (speedup 1.0000x reference)
#include <cuda_runtime.h>
#include <cuda_bf16.h>

#define D 512
#define H 128
#define NROW 262143               // path rows
#define MBLK 32
#define NBLK ((NROW + MBLK - 1) / MBLK)   // 8192
#define GRID1 152

// ---------------- scratch (no allocations allowed) ----------------
__device__ float g_basep[16 * H];
__device__ float g_aggp[GRID1 * D];
__device__ float g_attnp[GRID1];
__device__ float g_comb[2 * D];
__device__ float g_p3[32 * D];
__device__ float g_gate[D];
__device__ float g_hidden[D];
__device__ float g_p5[16 * D];

// ---------------- smem layout for main kernel ----------------
#define SWT_STR 520   // bf16 elems per row (1040B stride -> conflict-free ldmatrix)
#define SA_STR  520
#define SA_ELEMS (MBLK * SA_STR)                   // 16640 bf16 per buffer
#define OFF_SWT  0
#define OFF_SA   (H * SWT_STR * 2)                 // 133120
#define OFF_PART (OFF_SA + 2 * SA_ELEMS * 2)       // 199680  [2][32][2] f32
#define OFF_ATTN (OFF_PART + 2 * 32 * 2 * 4)       // 200192  [2][32] f32
#define OFF_BASE (OFF_ATTN + 2 * 32 * 4)           // 200448
#define OFF_W2   (OFF_BASE + H * 4)                // 200960
#define SMEM_SZ  (OFF_W2 + H * 4)                  // 201472

// named barriers: FULL=1+b, DONE=3+b, ATTN=5+b (count 256), EPI=7 (count 128)
#define BAR_SYNC(id)   asm volatile("bar.sync %0, 256;"   :: "r"(id) : "memory")
#define BAR_ARRIVE(id) asm volatile("bar.arrive %0, 256;" :: "r"(id) : "memory")
#define BAR_SYNC_C(id) asm volatile("bar.sync %0, 128;"   :: "r"(id) : "memory")

__device__ __forceinline__ void mma16816(float c[4], const unsigned a[4],
                                         unsigned b0, unsigned b1) {
    asm("mma.sync.aligned.m16n8k16.row.col.f32.bf16.bf16.f32 "
        "{%0,%1,%2,%3}, {%4,%5,%6,%7}, {%8,%9}, {%0,%1,%2,%3};\n"
        : "+f"(c[0]), "+f"(c[1]), "+f"(c[2]), "+f"(c[3])
        : "r"(a[0]), "r"(a[1]), "r"(a[2]), "r"(a[3]), "r"(b0), "r"(b1));
}

__device__ __forceinline__ void ldsm4(unsigned r[4], unsigned addr) {
    asm volatile("ldmatrix.sync.aligned.m8n8.x4.shared.b16 {%0,%1,%2,%3}, [%4];"
        : "=r"(r[0]), "=r"(r[1]), "=r"(r[2]), "=r"(r[3]) : "r"(addr));
}

// ---------------- K0: partial base[j] = target @ aW1[:D] (16-way split) ----------------
__global__ void k_basep(const float* __restrict__ f, const float* __restrict__ aW1) {
    int b = blockIdx.x;        // 16 blocks
    int j = threadIdx.x;       // 128 threads
    int k0 = b * 32;
    float acc = 0.f;
    for (int k = k0; k < k0 + 32; k++) acc += f[k] * aW1[k * H + j];
    g_basep[b * H + j] = acc;
}

// ---------------- K1: warp-specialized fused copy + GEMM + attn + weighted-sum ----------------
__global__ void __launch_bounds__(256, 1)
k_main(const float* __restrict__ features, const float* __restrict__ aW1,
       const float* __restrict__ ab1, const float* __restrict__ aW2,
       const float* __restrict__ ab2, float* __restrict__ out) {
    extern __shared__ char smem[];
    __nv_bfloat16* sWt = (__nv_bfloat16*)(smem + OFF_SWT);   // [128][520] W^T (n-major)
    __nv_bfloat16* sA  = (__nv_bfloat16*)(smem + OFF_SA);    // 2 x [32][520] tiles
    float* sPart = (float*)(smem + OFF_PART);                // [2][32][2]
    float* sAttn = (float*)(smem + OFF_ATTN);                // [2][32]
    float* sBase = (float*)(smem + OFF_BASE);                // [128]
    float* sW2   = (float*)(smem + OFF_W2);                  // [128]

    int tid = threadIdx.x;

    // init: W^T into smem as bf16, base/w2
    for (int idx = tid; idx < D * H; idx += 256) {
        int k = idx >> 7, n = idx & 127;
        sWt[n * SWT_STR + k] = __float2bfloat16(aW1[(D + k) * H + n]);
    }
    if (tid < H) {
        float s = ab1[tid];
#pragma unroll
        for (int bb = 0; bb < 16; bb++) s += g_basep[bb * H + tid];
        sBase[tid] = s;
        sW2[tid] = aW2[tid];
    }
    __syncthreads();

    if (tid < 128) {
        // =============== CONSUMERS: GEMM + attn ===============
        int warp = tid >> 5, lane = tid & 31;
        int wm = warp & 1, wn = warp >> 1;
        int g = lane >> 2, tg = lane & 3;
        unsigned sA_u = (unsigned)__cvta_generic_to_shared(sA);
        unsigned sW_u = (unsigned)__cvta_generic_to_shared(sWt);
        unsigned aAddr = sA_u + (unsigned)(((wm * 16 + (lane & 15)) * SA_STR + ((lane >> 4) << 3)) * 2);
        unsigned bAddr = sW_u + (unsigned)(((wn * 64 + ((lane >> 4) << 3) + (lane & 7)) * SWT_STR
                                            + (((lane >> 3) & 1) << 3)) * 2);
        float baseR[16], w2R[16];
#pragma unroll
        for (int f = 0; f < 8; f++) {
            int col = wn * 64 + (f >> 1) * 16 + (f & 1) * 8 + tg * 2;
            baseR[f * 2]     = sBase[col];   baseR[f * 2 + 1] = sBase[col + 1];
            w2R[f * 2]       = sW2[col];     w2R[f * 2 + 1]   = sW2[col + 1];
        }
        float ab2v = ab2[0];
        float tot = 0.f;

        int j = 0;
        for (long tile = blockIdx.x; tile < NBLK; tile += GRID1, j++) {
            int b = j & 1;
            unsigned aA = aAddr + (unsigned)(b * SA_ELEMS * 2);
            BAR_SYNC(1 + b);                        // FULL: tile ready

            float c[8][4];
#pragma unroll
            for (int f = 0; f < 8; f++)
#pragma unroll
                for (int q = 0; q < 4; q++) c[f][q] = 0.f;

#pragma unroll 4
            for (int k0 = 0; k0 < D; k0 += 16) {
                unsigned aF[4];
                ldsm4(aF, aA + k0 * 2);
#pragma unroll
                for (int nt = 0; nt < 4; nt++) {
                    unsigned bF[4];
                    ldsm4(bF, bAddr + (unsigned)((nt * 16 * SWT_STR + k0) * 2));
                    mma16816(c[nt * 2],     aF, bF[0], bF[1]);
                    mma16816(c[nt * 2 + 1], aF, bF[2], bF[3]);
                }
            }
            BAR_ARRIVE(3 + b);                      // DONE: buffer b reusable

            // epilogue: per-row partial sum over this warp's 64 cols
            float pe = 0.f, po = 0.f;
#pragma unroll
            for (int f = 0; f < 8; f++) {
                pe += fmaxf(baseR[f * 2]     + c[f][0], 0.f) * w2R[f * 2];
                pe += fmaxf(baseR[f * 2 + 1] + c[f][1], 0.f) * w2R[f * 2 + 1];
                po += fmaxf(baseR[f * 2]     + c[f][2], 0.f) * w2R[f * 2];
                po += fmaxf(baseR[f * 2 + 1] + c[f][3], 0.f) * w2R[f * 2 + 1];
            }
            pe += __shfl_xor_sync(0xffffffffu, pe, 1);
            pe += __shfl_xor_sync(0xffffffffu, pe, 2);
            po += __shfl_xor_sync(0xffffffffu, po, 1);
            po += __shfl_xor_sync(0xffffffffu, po, 2);
            if (tg == 0) {
                int row = wm * 16 + g;
                sPart[(b * 32 + row) * 2 + wn]     = pe;
                sPart[(b * 32 + row + 8) * 2 + wn] = po;
            }
            BAR_SYNC_C(7);                          // EPI (consumers only)
            if (warp == 0) {
                float s = sPart[(b * 32 + lane) * 2] + sPart[(b * 32 + lane) * 2 + 1] + ab2v;
                float a = 1.f / (1.f + __expf(-s));
                if (tile * MBLK + lane >= NROW) a = 0.f;
                sAttn[b * 32 + lane] = a;
                float vv = a;
#pragma unroll
                for (int o = 16; o; o >>= 1) vv += __shfl_xor_sync(0xffffffffu, vv, o);
                tot += vv;
            }
            __threadfence_block();
            BAR_ARRIVE(5 + b);                      // ATTN ready
        }
        if (warp == 0 && lane == 0) g_attnp[blockIdx.x] = tot;
    } else {
        // =============== PRODUCERS: copy + stage + agg ===============
        int ptid = tid - 128;                       // 0..127 = float4 column
        float agg[4] = {0.f, 0.f, 0.f, 0.f};
        const float4* fbase = (const float4*)features;
        float4* obase = (float4*)out;
        float4 v[32];

        int j = 0;
        for (long tile = blockIdx.x; tile < NBLK; tile += GRID1, j++) {
            int b = j & 1;
            long rowbase = tile * MBLK;
            bool full = (rowbase + MBLK <= NROW);

            // issue loads for this tile (overlap with agg of previous tile)
            if (full) {
#pragma unroll
                for (int r = 0; r < 32; r++)
                    v[r] = __ldcs(fbase + (rowbase + r + 1) * (D / 4) + ptid);
            } else {
#pragma unroll
                for (int r = 0; r < 32; r++) {
                    long prow = rowbase + r;
                    v[r] = (prow < NROW) ? __ldcs(fbase + (prow + 1) * (D / 4) + ptid)
                                         : make_float4(0.f, 0.f, 0.f, 0.f);
                }
            }

            // agg for previous tile (reads own STS data + attn from consumers)
            if (j > 0) {
                int pb = 1 - b;
                BAR_SYNC(5 + pb);                   // ATTN prev ready
                const __nv_bfloat16* A = sA + pb * SA_ELEMS;
#pragma unroll 4
                for (int r = 0; r < 32; r++) {
                    float a = sAttn[pb * 32 + r];
                    uint2 pk = *(const uint2*)(A + r * SA_STR + ptid * 4);
                    __nv_bfloat162 lo = *(__nv_bfloat162*)&pk.x;
                    __nv_bfloat162 hi = *(__nv_bfloat162*)&pk.y;
                    float2 l = __bfloat1622float2(lo);
                    float2 h = __bfloat1622float2(hi);
                    agg[0] += a * l.x; agg[1] += a * l.y;
                    agg[2] += a * h.x; agg[3] += a * h.y;
                }
            }
            if (j >= 2) BAR_SYNC(3 + b);            // DONE: consumers off buffer b

            // drain: copy to out + bf16 tile into smem
            __nv_bfloat16* Ab = sA + b * SA_ELEMS;
            if (full) {
#pragma unroll
                for (int r = 0; r < 32; r++) {
                    float4 w = v[r];
                    __stcs(obase + (rowbase + r + 1) * (D / 4) + ptid, w);
                    __nv_bfloat162 lo = __floats2bfloat162_rn(w.x, w.y);
                    __nv_bfloat162 hi = __floats2bfloat162_rn(w.z, w.w);
                    uint2 pk; pk.x = *(unsigned*)&lo; pk.y = *(unsigned*)&hi;
                    *(uint2*)(Ab + r * SA_STR + ptid * 4) = pk;
                }
            } else {
#pragma unroll
                for (int r = 0; r < 32; r++) {
                    float4 w = v[r];
                    long prow = rowbase + r;
                    if (prow < NROW)
                        __stcs(obase + (prow + 1) * (D / 4) + ptid, w);
                    __nv_bfloat162 lo = __floats2bfloat162_rn(w.x, w.y);
                    __nv_bfloat162 hi = __floats2bfloat162_rn(w.z, w.w);
                    uint2 pk; pk.x = *(unsigned*)&lo; pk.y = *(unsigned*)&hi;
                    *(uint2*)(Ab + r * SA_STR + ptid * 4) = pk;
                }
            }
            __threadfence_block();
            BAR_ARRIVE(1 + b);                      // FULL
        }

        // final agg for last tile
        {
            int bl = (j - 1) & 1;
            BAR_SYNC(5 + bl);
            const __nv_bfloat16* A = sA + bl * SA_ELEMS;
#pragma unroll 4
            for (int r = 0; r < 32; r++) {
                float a = sAttn[bl * 32 + r];
                uint2 pk = *(const uint2*)(A + r * SA_STR + ptid * 4);
                __nv_bfloat162 lo = *(__nv_bfloat162*)&pk.x;
                __nv_bfloat162 hi = *(__nv_bfloat162*)&pk.y;
                float2 l = __bfloat1622float2(lo);
                float2 h = __bfloat1622float2(hi);
                agg[0] += a * l.x; agg[1] += a * l.y;
                agg[2] += a * h.x; agg[3] += a * h.y;
            }
        }
#pragma unroll
        for (int e = 0; e < 4; e++)
            g_aggp[blockIdx.x * D + ptid * 4 + e] = agg[e];
    }
}

// ---------------- K2: reduce partials, build comb = [target, agg/s] ----------------
__global__ void k_reduce(const float* __restrict__ features) {
    __shared__ float red[64];
    int j = blockIdx.x * 64 + threadIdx.x;   // 8 blocks x 64 threads
    float acc = 0.f;
#pragma unroll 4
    for (int i = 0; i < GRID1; i++) acc += g_aggp[i * D + j];
    float sp = 0.f;
    for (int i = threadIdx.x; i < GRID1; i += 64) sp += g_attnp[i];
    red[threadIdx.x] = sp;
    __syncthreads();
#pragma unroll
    for (int o = 32; o; o >>= 1) {
        if (threadIdx.x < o) red[threadIdx.x] += red[threadIdx.x + o];
        __syncthreads();
    }
    float s = red[0];
    g_comb[j] = features[j];                       // target
    g_comb[D + j] = (s > 0.f) ? acc / s : acc;     // agg
}

// ---------------- K3: partial dots for gate (gW) and hidden (uW1) ----------------
__global__ void k_mid(const float* __restrict__ gW, const float* __restrict__ uW1) {
    __shared__ float sc[64];
    __shared__ float red[4][64];
    int b = blockIdx.x;                 // 256 blocks: mat(2) x kc(16) x cc(8)
    int mat = b >> 7, kc = (b >> 3) & 15, cc = b & 7;
    const float* W = mat ? uW1 : gW;
    int ks = kc * 64, c0 = cc * 64;
    if (threadIdx.x < 64) sc[threadIdx.x] = g_comb[ks + threadIdx.x];
    __syncthreads();
    int ci = threadIdx.x & 63, kq = threadIdx.x >> 6;
    int c = c0 + ci;
    float a = 0.f;
#pragma unroll
    for (int kk = 0; kk < 16; kk++) {
        int k = ks + kq * 16 + kk;
        a += sc[kq * 16 + kk] * W[k * D + c];
    }
    red[kq][ci] = a;
    __syncthreads();
    if (threadIdx.x < 64)
        g_p3[(mat * 16 + kc) * D + c0 + threadIdx.x] =
            red[0][threadIdx.x] + red[1][threadIdx.x] + red[2][threadIdx.x] + red[3][threadIdx.x];
}

// ---------------- K4: gate = sigmoid(.+gb), hidden = relu(.+ub1) ----------------
__global__ void k_act(const float* __restrict__ gb, const float* __restrict__ ub1) {
    int j = threadIdx.x;   // 512
    float gs = 0.f, hs = 0.f;
#pragma unroll
    for (int b = 0; b < 16; b++)  gs += g_p3[b * D + j];
#pragma unroll
    for (int b = 16; b < 32; b++) hs += g_p3[b * D + j];
    g_gate[j] = 1.f / (1.f + __expf(-(gs + gb[j])));
    g_hidden[j] = fmaxf(hs + ub1[j], 0.f);
}

// ---------------- K5: partial dots for upd (uW2) ----------------
__global__ void k_upd(const float* __restrict__ uW2) {
    __shared__ float sh[32];
    __shared__ float red[4][64];
    int b = blockIdx.x;       // 128 blocks: kc(16) x cc(8)
    int kc = b >> 3, cc = b & 7;
    int ks = kc * 32, c0 = cc * 64;
    if (threadIdx.x < 32) sh[threadIdx.x] = g_hidden[ks + threadIdx.x];
    __syncthreads();
    int ci = threadIdx.x & 63, kq = threadIdx.x >> 6;
    int c = c0 + ci;
    float a = 0.f;
#pragma unroll
    for (int kk = 0; kk < 8; kk++) {
        int k = ks + kq * 8 + kk;
        a += sh[kq * 8 + kk] * uW2[k * D + c];
    }
    red[kq][ci] = a;
    __syncthreads();
    if (threadIdx.x < 64)
        g_p5[kc * D + c0 + threadIdx.x] =
            red[0][threadIdx.x] + red[1][threadIdx.x] + red[2][threadIdx.x] + red[3][threadIdx.x];
}

// ---------------- K6: out row 0 = target + gate * (upd + ub2) ----------------
__global__ void k_fin(const float* __restrict__ features, const float* __restrict__ ub2,
                      float* __restrict__ out) {
    int j = threadIdx.x;   // 512
    float u = 0.f;
#pragma unroll
    for (int b = 0; b < 16; b++) u += g_p5[b * D + j];
    u += ub2[0];
    out[j] = features[j] + g_gate[j] * u;
}

extern "C" void kernel_launch(void* const* d_in, const int* in_sizes, int n_in,
                              void* d_out, int out_size) {
    const float* features = (const float*)d_in[0];
    const float* aW1 = (const float*)d_in[1];
    const float* ab1 = (const float*)d_in[2];
    const float* aW2 = (const float*)d_in[3];
    const float* ab2 = (const float*)d_in[4];
    const float* uW1 = (const float*)d_in[5];
    const float* ub1 = (const float*)d_in[6];
    const float* uW2 = (const float*)d_in[7];
    const float* ub2 = (const float*)d_in[8];
    const float* gW  = (const float*)d_in[9];
    const float* gb  = (const float*)d_in[10];
    float* out = (float*)d_out;

    cudaFuncSetAttribute(k_main, cudaFuncAttributeMaxDynamicSharedMemorySize, SMEM_SZ);

    k_basep<<<16, 128>>>(features, aW1);
    k_main<<<GRID1, 256, SMEM_SZ>>>(features, aW1, ab1, aW2, ab2, out);
    k_reduce<<<8, 64>>>(features);
    k_mid<<<256, 256>>>(gW, uW1);
    k_act<<<1, 512>>>(gb, ub1);
    k_upd<<<128, 256>>>(uW2);
    k_fin<<<1, 512>>>(features, ub2, out);
}

// round 4
// speedup vs baseline: 1.2082x; 1.2082x over previous
#include <cuda_runtime.h>
#include <cuda_bf16.h>

#define D 512
#define H 128
#define NROW 262143               // path rows
#define MBLK 32
#define NBLK ((NROW + MBLK - 1) / MBLK)   // 8192
#define GRID1 152

// ---------------- scratch (no allocations allowed) ----------------
__device__ float g_basep[16 * H];
__device__ float g_aggp[GRID1 * D];
__device__ float g_attnp[GRID1];
__device__ float g_comb[2 * D];
__device__ float g_p3[32 * D];
__device__ float g_gate[D];
__device__ float g_hidden[D];
__device__ float g_p5[16 * D];

// ---------------- smem layout for main kernel ----------------
#define SWT_STR 520   // bf16 elems per row (1040B stride -> conflict-free ldmatrix)
#define SA_STR  520
#define SA_ELEMS (MBLK * SA_STR)                   // 16640 bf16 per buffer
#define OFF_SWT  0
#define OFF_SA   (H * SWT_STR * 2)                 // 133120
#define OFF_PART (OFF_SA + 2 * SA_ELEMS * 2)       // 199680  [2][32][2] f32
#define OFF_ATTN (OFF_PART + 2 * 32 * 2 * 4)       // 200192  [2][32] f32
#define OFF_BASE (OFF_ATTN + 2 * 32 * 4)           // 200448
#define OFF_W2   (OFF_BASE + H * 4)                // 200960
#define SMEM_SZ  (OFF_W2 + H * 4)                  // 201472

// named barriers: FULL=1+b, DONE=3+b, ATTN=5+b (count 256), EPI=7 (count 128)
#define BAR_SYNC(id)   asm volatile("bar.sync %0, 256;"   :: "r"(id) : "memory")
#define BAR_ARRIVE(id) asm volatile("bar.arrive %0, 256;" :: "r"(id) : "memory")
#define BAR_SYNC_C(id) asm volatile("bar.sync %0, 128;"   :: "r"(id) : "memory")

__device__ __forceinline__ void mma16816(float c[4], const unsigned a[4],
                                         unsigned b0, unsigned b1) {
    asm("mma.sync.aligned.m16n8k16.row.col.f32.bf16.bf16.f32 "
        "{%0,%1,%2,%3}, {%4,%5,%6,%7}, {%8,%9}, {%0,%1,%2,%3};\n"
        : "+f"(c[0]), "+f"(c[1]), "+f"(c[2]), "+f"(c[3])
        : "r"(a[0]), "r"(a[1]), "r"(a[2]), "r"(a[3]), "r"(b0), "r"(b1));
}

__device__ __forceinline__ void ldsm4(unsigned r[4], unsigned addr) {
    asm volatile("ldmatrix.sync.aligned.m8n8.x4.shared.b16 {%0,%1,%2,%3}, [%4];"
        : "=r"(r[0]), "=r"(r[1]), "=r"(r[2]), "=r"(r[3]) : "r"(addr));
}

// ---------------- K0: partial base[j] = target @ aW1[:D] (16-way split) ----------------
__global__ void k_basep(const float* __restrict__ f, const float* __restrict__ aW1) {
    int b = blockIdx.x;        // 16 blocks
    int j = threadIdx.x;       // 128 threads
    int k0 = b * 32;
    float acc = 0.f;
    for (int k = k0; k < k0 + 32; k++) acc += f[k] * aW1[k * H + j];
    g_basep[b * H + j] = acc;
}

// ---------------- K1: warp-specialized fused copy + GEMM + attn + weighted-sum ----------------
__global__ void __launch_bounds__(256, 1)
k_main(const float* __restrict__ features, const float* __restrict__ aW1,
       const float* __restrict__ ab1, const float* __restrict__ aW2,
       const float* __restrict__ ab2, float* __restrict__ out) {
    extern __shared__ char smem[];
    __nv_bfloat16* sWt = (__nv_bfloat16*)(smem + OFF_SWT);   // [128][520] W^T (n-major)
    __nv_bfloat16* sA  = (__nv_bfloat16*)(smem + OFF_SA);    // 2 x [32][520] tiles
    float* sPart = (float*)(smem + OFF_PART);                // [2][32][2]
    float* sAttn = (float*)(smem + OFF_ATTN);                // [2][32]
    float* sBase = (float*)(smem + OFF_BASE);                // [128]
    float* sW2   = (float*)(smem + OFF_W2);                  // [128]

    int tid = threadIdx.x;

    // init: W^T into smem as bf16, base/w2
    for (int idx = tid; idx < D * H; idx += 256) {
        int k = idx >> 7, n = idx & 127;
        sWt[n * SWT_STR + k] = __float2bfloat16(aW1[(D + k) * H + n]);
    }
    if (tid < H) {
        float s = ab1[tid];
#pragma unroll
        for (int bb = 0; bb < 16; bb++) s += g_basep[bb * H + tid];
        sBase[tid] = s;
        sW2[tid] = aW2[tid];
    }
    __syncthreads();

    if (tid < 128) {
        // =============== CONSUMERS: GEMM + attn ===============
        int warp = tid >> 5, lane = tid & 31;
        int wm = warp & 1, wn = warp >> 1;
        int g = lane >> 2, tg = lane & 3;
        unsigned sA_u = (unsigned)__cvta_generic_to_shared(sA);
        unsigned sW_u = (unsigned)__cvta_generic_to_shared(sWt);
        unsigned aAddr = sA_u + (unsigned)(((wm * 16 + (lane & 15)) * SA_STR + ((lane >> 4) << 3)) * 2);
        unsigned bAddr = sW_u + (unsigned)(((wn * 64 + ((lane >> 4) << 3) + (lane & 7)) * SWT_STR
                                            + (((lane >> 3) & 1) << 3)) * 2);
        float baseR[16], w2R[16];
#pragma unroll
        for (int f = 0; f < 8; f++) {
            int col = wn * 64 + (f >> 1) * 16 + (f & 1) * 8 + tg * 2;
            baseR[f * 2]     = sBase[col];   baseR[f * 2 + 1] = sBase[col + 1];
            w2R[f * 2]       = sW2[col];     w2R[f * 2 + 1]   = sW2[col + 1];
        }
        float ab2v = ab2[0];
        float tot = 0.f;

        int j = 0;
        for (long tile = blockIdx.x; tile < NBLK; tile += GRID1, j++) {
            int b = j & 1;
            unsigned aA = aAddr + (unsigned)(b * SA_ELEMS * 2);
            BAR_SYNC(1 + b);                        // FULL: tile ready

            float c[8][4];
#pragma unroll
            for (int f = 0; f < 8; f++)
#pragma unroll
                for (int q = 0; q < 4; q++) c[f][q] = 0.f;

#pragma unroll 4
            for (int k0 = 0; k0 < D; k0 += 16) {
                unsigned aF[4];
                ldsm4(aF, aA + k0 * 2);
#pragma unroll
                for (int nt = 0; nt < 4; nt++) {
                    unsigned bF[4];
                    ldsm4(bF, bAddr + (unsigned)((nt * 16 * SWT_STR + k0) * 2));
                    mma16816(c[nt * 2],     aF, bF[0], bF[1]);
                    mma16816(c[nt * 2 + 1], aF, bF[2], bF[3]);
                }
            }
            BAR_ARRIVE(3 + b);                      // DONE: buffer b reusable

            // epilogue: per-row partial sum over this warp's 64 cols
            float pe = 0.f, po = 0.f;
#pragma unroll
            for (int f = 0; f < 8; f++) {
                pe += fmaxf(baseR[f * 2]     + c[f][0], 0.f) * w2R[f * 2];
                pe += fmaxf(baseR[f * 2 + 1] + c[f][1], 0.f) * w2R[f * 2 + 1];
                po += fmaxf(baseR[f * 2]     + c[f][2], 0.f) * w2R[f * 2];
                po += fmaxf(baseR[f * 2 + 1] + c[f][3], 0.f) * w2R[f * 2 + 1];
            }
            pe += __shfl_xor_sync(0xffffffffu, pe, 1);
            pe += __shfl_xor_sync(0xffffffffu, pe, 2);
            po += __shfl_xor_sync(0xffffffffu, po, 1);
            po += __shfl_xor_sync(0xffffffffu, po, 2);
            if (tg == 0) {
                int row = wm * 16 + g;
                sPart[(b * 32 + row) * 2 + wn]     = pe;
                sPart[(b * 32 + row + 8) * 2 + wn] = po;
            }
            BAR_SYNC_C(7);                          // EPI (consumers only)
            if (warp == 0) {
                float s = sPart[(b * 32 + lane) * 2] + sPart[(b * 32 + lane) * 2 + 1] + ab2v;
                float a = 1.f / (1.f + __expf(-s));
                if (tile * MBLK + lane >= NROW) a = 0.f;
                sAttn[b * 32 + lane] = a;
                float vv = a;
#pragma unroll
                for (int o = 16; o; o >>= 1) vv += __shfl_xor_sync(0xffffffffu, vv, o);
                tot += vv;
            }
            __threadfence_block();
            BAR_ARRIVE(5 + b);                      // ATTN ready
        }
        if (warp == 0 && lane == 0) g_attnp[blockIdx.x] = tot;
    } else {
        // =============== PRODUCERS: copy + stage + agg ===============
        int ptid = tid - 128;                       // 0..127 = float4 column
        float agg[4] = {0.f, 0.f, 0.f, 0.f};
        const float4* fbase = (const float4*)features;
        float4* obase = (float4*)out;
        float4 va[8], vb[8];

        auto loadc = [&](float4* v, long rowbase, int r0) {
#pragma unroll
            for (int r = 0; r < 8; r++) {
                long prow = rowbase + r0 + r;
                v[r] = (prow < NROW) ? __ldcs(fbase + (prow + 1) * (D / 4) + ptid)
                                     : make_float4(0.f, 0.f, 0.f, 0.f);
            }
        };
        auto drainc = [&](const float4* v, __nv_bfloat16* Ab, long rowbase, int r0) {
#pragma unroll
            for (int r = 0; r < 8; r++) {
                long prow = rowbase + r0 + r;
                float4 w = v[r];
                if (prow < NROW)
                    __stcs(obase + (prow + 1) * (D / 4) + ptid, w);
                __nv_bfloat162 lo = __floats2bfloat162_rn(w.x, w.y);
                __nv_bfloat162 hi = __floats2bfloat162_rn(w.z, w.w);
                uint2 pk; pk.x = *(unsigned*)&lo; pk.y = *(unsigned*)&hi;
                *(uint2*)(Ab + (r0 + r) * SA_STR + ptid * 4) = pk;
            }
        };

        int j = 0;
        for (long tile = blockIdx.x; tile < NBLK; tile += GRID1, j++) {
            int b = j & 1;
            long rowbase = tile * MBLK;
            __nv_bfloat16* Ab = sA + b * SA_ELEMS;

            // pipelined load+drain: buffer b must be free (DONE) before STS
            loadc(va, rowbase, 0);
            loadc(vb, rowbase, 8);
            if (j >= 2) BAR_SYNC(3 + b);            // DONE: consumers off buffer b
            drainc(va, Ab, rowbase, 0);
            loadc(va, rowbase, 16);
            drainc(vb, Ab, rowbase, 8);
            loadc(vb, rowbase, 24);
            drainc(va, Ab, rowbase, 16);
            drainc(vb, Ab, rowbase, 24);
            __threadfence_block();
            BAR_ARRIVE(1 + b);                      // FULL -> consumers start GEMM(j)

            // agg for previous tile (runs concurrently with consumer GEMM(j))
            if (j > 0) {
                int pb = 1 - b;
                BAR_SYNC(5 + pb);                   // ATTN(j-1) ready
                const __nv_bfloat16* A = sA + pb * SA_ELEMS;
#pragma unroll 4
                for (int r = 0; r < 32; r++) {
                    float a = sAttn[pb * 32 + r];
                    uint2 pk = *(const uint2*)(A + r * SA_STR + ptid * 4);
                    __nv_bfloat162 lo = *(__nv_bfloat162*)&pk.x;
                    __nv_bfloat162 hi = *(__nv_bfloat162*)&pk.y;
                    float2 l = __bfloat1622float2(lo);
                    float2 h = __bfloat1622float2(hi);
                    agg[0] += a * l.x; agg[1] += a * l.y;
                    agg[2] += a * h.x; agg[3] += a * h.y;
                }
            }
        }

        // final agg for last tile
        {
            int bl = (j - 1) & 1;
            BAR_SYNC(5 + bl);
            const __nv_bfloat16* A = sA + bl * SA_ELEMS;
#pragma unroll 4
            for (int r = 0; r < 32; r++) {
                float a = sAttn[bl * 32 + r];
                uint2 pk = *(const uint2*)(A + r * SA_STR + ptid * 4);
                __nv_bfloat162 lo = *(__nv_bfloat162*)&pk.x;
                __nv_bfloat162 hi = *(__nv_bfloat162*)&pk.y;
                float2 l = __bfloat1622float2(lo);
                float2 h = __bfloat1622float2(hi);
                agg[0] += a * l.x; agg[1] += a * l.y;
                agg[2] += a * h.x; agg[3] += a * h.y;
            }
        }
#pragma unroll
        for (int e = 0; e < 4; e++)
            g_aggp[blockIdx.x * D + ptid * 4 + e] = agg[e];
    }
}

// ---------------- K2: reduce partials, build comb = [target, agg/s] ----------------
__global__ void k_reduce(const float* __restrict__ features) {
    __shared__ float red[64];
    int j = blockIdx.x * 64 + threadIdx.x;   // 8 blocks x 64 threads
    float acc = 0.f;
#pragma unroll 4
    for (int i = 0; i < GRID1; i++) acc += g_aggp[i * D + j];
    float sp = 0.f;
    for (int i = threadIdx.x; i < GRID1; i += 64) sp += g_attnp[i];
    red[threadIdx.x] = sp;
    __syncthreads();
#pragma unroll
    for (int o = 32; o; o >>= 1) {
        if (threadIdx.x < o) red[threadIdx.x] += red[threadIdx.x + o];
        __syncthreads();
    }
    float s = red[0];
    g_comb[j] = features[j];                       // target
    g_comb[D + j] = (s > 0.f) ? acc / s : acc;     // agg
}

// ---------------- K3: partial dots for gate (gW) and hidden (uW1) ----------------
__global__ void k_mid(const float* __restrict__ gW, const float* __restrict__ uW1) {
    __shared__ float sc[64];
    __shared__ float red[4][64];
    int b = blockIdx.x;                 // 256 blocks: mat(2) x kc(16) x cc(8)
    int mat = b >> 7, kc = (b >> 3) & 15, cc = b & 7;
    const float* W = mat ? uW1 : gW;
    int ks = kc * 64, c0 = cc * 64;
    if (threadIdx.x < 64) sc[threadIdx.x] = g_comb[ks + threadIdx.x];
    __syncthreads();
    int ci = threadIdx.x & 63, kq = threadIdx.x >> 6;
    int c = c0 + ci;
    float a = 0.f;
#pragma unroll
    for (int kk = 0; kk < 16; kk++) {
        int k = ks + kq * 16 + kk;
        a += sc[kq * 16 + kk] * W[k * D + c];
    }
    red[kq][ci] = a;
    __syncthreads();
    if (threadIdx.x < 64)
        g_p3[(mat * 16 + kc) * D + c0 + threadIdx.x] =
            red[0][threadIdx.x] + red[1][threadIdx.x] + red[2][threadIdx.x] + red[3][threadIdx.x];
}

// ---------------- K4: gate = sigmoid(.+gb), hidden = relu(.+ub1) ----------------
__global__ void k_act(const float* __restrict__ gb, const float* __restrict__ ub1) {
    int j = threadIdx.x;   // 512
    float gs = 0.f, hs = 0.f;
#pragma unroll
    for (int b = 0; b < 16; b++)  gs += g_p3[b * D + j];
#pragma unroll
    for (int b = 16; b < 32; b++) hs += g_p3[b * D + j];
    g_gate[j] = 1.f / (1.f + __expf(-(gs + gb[j])));
    g_hidden[j] = fmaxf(hs + ub1[j], 0.f);
}

// ---------------- K5: partial dots for upd (uW2) ----------------
__global__ void k_upd(const float* __restrict__ uW2) {
    __shared__ float sh[32];
    __shared__ float red[4][64];
    int b = blockIdx.x;       // 128 blocks: kc(16) x cc(8)
    int kc = b >> 3, cc = b & 7;
    int ks = kc * 32, c0 = cc * 64;
    if (threadIdx.x < 32) sh[threadIdx.x] = g_hidden[ks + threadIdx.x];
    __syncthreads();
    int ci = threadIdx.x & 63, kq = threadIdx.x >> 6;
    int c = c0 + ci;
    float a = 0.f;
#pragma unroll
    for (int kk = 0; kk < 8; kk++) {
        int k = ks + kq * 8 + kk;
        a += sh[kq * 8 + kk] * uW2[k * D + c];
    }
    red[kq][ci] = a;
    __syncthreads();
    if (threadIdx.x < 64)
        g_p5[kc * D + c0 + threadIdx.x] =
            red[0][threadIdx.x] + red[1][threadIdx.x] + red[2][threadIdx.x] + red[3][threadIdx.x];
}

// ---------------- K6: out row 0 = target + gate * (upd + ub2) ----------------
__global__ void k_fin(const float* __restrict__ features, const float* __restrict__ ub2,
                      float* __restrict__ out) {
    int j = threadIdx.x;   // 512
    float u = 0.f;
#pragma unroll
    for (int b = 0; b < 16; b++) u += g_p5[b * D + j];
    u += ub2[0];
    out[j] = features[j] + g_gate[j] * u;
}

extern "C" void kernel_launch(void* const* d_in, const int* in_sizes, int n_in,
                              void* d_out, int out_size) {
    const float* features = (const float*)d_in[0];
    const float* aW1 = (const float*)d_in[1];
    const float* ab1 = (const float*)d_in[2];
    const float* aW2 = (const float*)d_in[3];
    const float* ab2 = (const float*)d_in[4];
    const float* uW1 = (const float*)d_in[5];
    const float* ub1 = (const float*)d_in[6];
    const float* uW2 = (const float*)d_in[7];
    const float* ub2 = (const float*)d_in[8];
    const float* gW  = (const float*)d_in[9];
    const float* gb  = (const float*)d_in[10];
    float* out = (float*)d_out;

    cudaFuncSetAttribute(k_main, cudaFuncAttributeMaxDynamicSharedMemorySize, SMEM_SZ);

    k_basep<<<16, 128>>>(features, aW1);
    k_main<<<GRID1, 256, SMEM_SZ>>>(features, aW1, ab1, aW2, ab2, out);
    k_reduce<<<8, 64>>>(features);
    k_mid<<<256, 256>>>(gW, uW1);
    k_act<<<1, 512>>>(gb, ub1);
    k_upd<<<128, 256>>>(uW2);
    k_fin<<<1, 512>>>(features, ub2, out);
}